// round 12
// baseline (speedup 1.0000x reference)
#include <cuda_runtime.h>

// DenseTNT postprocess: per-batch greedy NMS over 4096 goal candidates.
// k-th pick = argmax score among candidates not suppressed (d2 < 4.0) by
// already-picked goals. Key = (ordered_float(score) << 32) | (~idx) encodes
// stable-sort tie-break (equal score -> lower original index).
//
// Final structure (best device-time variant):
//  - lazy suppression: each thread contributes only its current local best;
//    per-round common path is ONE distance check
//  - one __syncthreads per round, parity-double-buffered warp partials
//  - gather warps ISSUE trajectory LDGs into a register buffer during the
//    rounds (no dependent STG -> no DRAM stall inside the barrier chain)
//  - scores stored in-round by thread m (all threads compute the winner);
//    NO epilogue smem, NO trailing barriers.

#define B_       128
#define N_       4096
#define MODES_   6
#define THRESH2_ 4.0f
#define TPB_     512
#define PER_     8           // candidates per thread (contiguous chunk)
#define NW_      (TPB_ / 32) // 16 warps

typedef unsigned long long u64;

__global__ __launch_bounds__(TPB_, 1)
void densetnt_nms_kernel(const float* __restrict__ scores,   // [B, N]
                         const float* __restrict__ trajs,    // [B, 60, N]
                         const float* __restrict__ goals,    // [B, 2, N]
                         float* __restrict__ out)            // [B,6,30,2] ++ [B,6]
{
    const int b    = blockIdx.x;
    const int t    = threadIdx.x;
    const int w    = t >> 5;
    const int lane = t & 31;

    __shared__ float2 sgoal[N_];          // 32 KB goal mirror (broadcast reads)
    __shared__ u64    red[2][NW_];        // parity double-buffer

    const float* sc = scores + (size_t)b * N_     + (size_t)t * PER_;
    const float* gx = goals  + (size_t)b * 2 * N_ + (size_t)t * PER_;
    const float* gy = gx + N_;
    const float* tb = trajs + (size_t)b * 60 * N_;
    float* ob = out + (size_t)b * MODES_ * 60;
    float* os_out = out + (size_t)B_ * MODES_ * 60 + (size_t)b * MODES_;

    // Vectorized load of this thread's contiguous 8-candidate chunk.
    float4 s0 = ((const float4*)sc)[0], s1 = ((const float4*)sc)[1];
    float4 a0 = ((const float4*)gx)[0], a1 = ((const float4*)gx)[1];
    float4 c0 = ((const float4*)gy)[0], c1 = ((const float4*)gy)[1];

    float x[PER_]  = {a0.x, a0.y, a0.z, a0.w, a1.x, a1.y, a1.z, a1.w};
    float y[PER_]  = {c0.x, c0.y, c0.z, c0.w, c1.x, c1.y, c1.z, c1.w};
    float sv[PER_] = {s0.x, s0.y, s0.z, s0.w, s1.x, s1.y, s1.z, s1.w};

    // Fill goal mirror with 4 STS.128.
    {
        float4* dst = (float4*)(sgoal + (size_t)t * PER_);
        dst[0] = make_float4(x[0], y[0], x[1], y[1]);
        dst[1] = make_float4(x[2], y[2], x[3], y[3]);
        dst[2] = make_float4(x[4], y[4], x[5], y[5]);
        dst[3] = make_float4(x[6], y[6], x[7], y[7]);
    }

    u64 key[PER_];
#pragma unroll
    for (int j = 0; j < PER_; j++) {
        unsigned i  = (unsigned)(t * PER_ + j);
        unsigned u  = __float_as_uint(sv[j]);
        unsigned os = u ^ (0x80000000u | (unsigned)(((int)u) >> 31)); // order-preserving
        key[j] = ((u64)os << 32) | (u64)(0xFFFFFFFFu - i);
    }

    // Initial local best (no picks yet -> no validation needed).
    u64 bk = key[0]; float bx = x[0], by = y[0];
#pragma unroll
    for (int j = 1; j < PER_; j++)
        if (key[j] > bk) { bk = key[j]; bx = x[j]; by = y[j]; }

    float px[MODES_], py[MODES_];   // pick history (static-indexed -> registers)
    float gbuf[MODES_];             // gather buffer (gather threads only)
    unsigned wmask = 0;             // bit m set <=> round m had a winner
    u64 win0 = 0ull;                // round-0 winner (fallback; provably != 0)

    const bool is_gather = (t >= TPB_ - 64) && (t - (TPB_ - 64) < 60);
    const int  ge        = t - (TPB_ - 64);   // gather element (valid if is_gather)

    __syncthreads();   // sgoal ready

#pragma unroll
    for (int m = 0; m < MODES_; m++) {
        // --- warp max over the 32 lazy local-bests (5 shfl levels) ---
        u64 best = bk;
#pragma unroll
        for (int o = 16; o > 0; o >>= 1) {
            u64 v = __shfl_xor_sync(0xFFFFFFFFu, best, o);
            best = v > best ? v : best;
        }
        if (lane == 0) red[m & 1][w] = best;
        __syncthreads();   // ONLY barrier this round

        // --- all threads merge the 16 warp partials (8x LDS.128) ---
        const ulonglong2* rp = (const ulonglong2*)red[m & 1];
        u64 win = 0ull;
#pragma unroll
        for (int q = 0; q < NW_ / 2; q++) {
            ulonglong2 p = rp[q];
            u64 hi = p.x > p.y ? p.x : p.y;
            win = hi > win ? hi : win;
        }
        if (m == 0) win0 = win;

        // --- in-round score store by thread m (fallback -> round-0 winner) ---
        if (t == m) {
            u64 wv = win ? win : win0;
            unsigned osv = (unsigned)(wv >> 32);
            os_out[m] = __uint_as_float(osv ^ (0x80000000u | (unsigned)(((int)~osv) >> 31)));
        }

        if (win != 0ull) {
            wmask |= 1u << m;
            const int widx = (int)(0xFFFFFFFFu - (unsigned)(win & 0xFFFFFFFFull));
            const float2 g = sgoal[widx];      // broadcast read
            px[m] = g.x; py[m] = g.y;

            // --- gather: ISSUE ONLY (value consumed after the loop) ---
            if (is_gather) gbuf[m] = __ldg(tb + (size_t)ge * N_ + widx);

            // --- lazy update of local best (skipped after the final pick) ---
            if (m < MODES_ - 1) {
                float dx = bx - g.x, dy = by - g.y;
                bool need = (bk == win) | (bk != 0ull && dx * dx + dy * dy < THRESH2_);
                if (need) {
#pragma unroll
                    for (int j = 0; j < PER_; j++) key[j] = (key[j] == bk) ? 0ull : key[j];
                    for (;;) {   // rare path: recompute + validate vs pick history
                        u64 nk = key[0]; float nx = x[0], ny = y[0];
#pragma unroll
                        for (int j = 1; j < PER_; j++)
                            if (key[j] > nk) { nk = key[j]; nx = x[j]; ny = y[j]; }
                        if (nk == 0ull) { bk = 0ull; break; }
                        bool sup = false;
#pragma unroll
                        for (int r = 0; r < MODES_; r++) {
                            if (r <= m) {
                                float ddx = nx - px[r], ddy = ny - py[r];
                                sup |= (ddx * ddx + ddy * ddy < THRESH2_);
                            }
                        }
                        if (sup) {
#pragma unroll
                            for (int j = 0; j < PER_; j++) key[j] = (key[j] == nk) ? 0ull : key[j];
                        } else { bk = nk; bx = nx; by = ny; break; }
                    }
                }
            }
        }
        // no trailing barrier: next round writes the other parity buffer; the
        // round-(m+1) barrier bounds warp skew to one round.
    }

    // --- gather flush: 6 STGs per gather thread; fallback modes reuse the
    //     round-0 value (round 0 always has a winner: all keys nonzero) ---
    if (is_gather) {
#pragma unroll
        for (int m = 0; m < MODES_; m++) {
            ob[m * 60 + ge] = (wmask & (1u << m)) ? gbuf[m] : gbuf[0];
        }
    }
}

extern "C" void kernel_launch(void* const* d_in, const int* in_sizes, int n_in,
                              void* d_out, int out_size)
{
    const float* goals_scores = (const float*)d_in[0];  // [128, 4096]
    const float* traj_preds   = (const float*)d_in[1];  // [128, 60, 4096]
    const float* pred_goals   = (const float*)d_in[2];  // [128, 2, 4096]
    float* out = (float*)d_out;

    densetnt_nms_kernel<<<B_, TPB_>>>(goals_scores, traj_preds, pred_goals, out);
}

// round 13
// speedup vs baseline: 1.0806x; 1.0806x over previous
#include <cuda_runtime.h>

// DenseTNT postprocess: per-batch greedy NMS over 4096 goal candidates.
// k-th pick = argmax score among candidates not suppressed (d2 < 4.0) by
// already-picked goals. Key = (ordered_float(score) << 32) | (~idx) encodes
// stable-sort tie-break (equal score -> lower index).
//
// LOCKED FINAL (R10 variant; tied-best measured device time 10.18us):
//  - lazy suppression: each thread contributes only its current local-best
//    candidate to the block argmax; per-round common path is ONE distance check
//  - one __syncthreads per round, parity-double-buffered warp partials
//  - gather warps ISSUE trajectory LDGs into a statically-indexed register
//    buffer during the rounds (no dependent STG -> no DRAM stall inside the
//    barrier-serialized round chain); single flush after the loop
//  - win_s[] epilogue for scores (in-round score stores measured slower).

#define B_       128
#define N_       4096
#define MODES_   6
#define THRESH2_ 4.0f
#define TPB_     512
#define PER_     8           // candidates per thread (contiguous chunk)
#define NW_      (TPB_ / 32) // 16 warps

typedef unsigned long long u64;

__global__ __launch_bounds__(TPB_, 1)
void densetnt_nms_kernel(const float* __restrict__ scores,   // [B, N]
                         const float* __restrict__ trajs,    // [B, 60, N]
                         const float* __restrict__ goals,    // [B, 2, N]
                         float* __restrict__ out)            // [B,6,30,2] ++ [B,6]
{
    const int b    = blockIdx.x;
    const int t    = threadIdx.x;
    const int w    = t >> 5;
    const int lane = t & 31;

    __shared__ float2 sgoal[N_];          // 32 KB goal mirror (broadcast reads)
    __shared__ u64    red[2][NW_];        // parity double-buffer
    __shared__ u64    win_s[MODES_];

    const float* sc = scores + (size_t)b * N_     + (size_t)t * PER_;
    const float* gx = goals  + (size_t)b * 2 * N_ + (size_t)t * PER_;
    const float* gy = gx + N_;
    const float* tb = trajs + (size_t)b * 60 * N_;
    float* ob = out + (size_t)b * MODES_ * 60;

    // Vectorized load of this thread's contiguous 8-candidate chunk.
    float4 s0 = ((const float4*)sc)[0], s1 = ((const float4*)sc)[1];
    float4 a0 = ((const float4*)gx)[0], a1 = ((const float4*)gx)[1];
    float4 c0 = ((const float4*)gy)[0], c1 = ((const float4*)gy)[1];

    float x[PER_]  = {a0.x, a0.y, a0.z, a0.w, a1.x, a1.y, a1.z, a1.w};
    float y[PER_]  = {c0.x, c0.y, c0.z, c0.w, c1.x, c1.y, c1.z, c1.w};
    float sv[PER_] = {s0.x, s0.y, s0.z, s0.w, s1.x, s1.y, s1.z, s1.w};

    // Fill goal mirror with 4 STS.128.
    {
        float4* dst = (float4*)(sgoal + (size_t)t * PER_);
        dst[0] = make_float4(x[0], y[0], x[1], y[1]);
        dst[1] = make_float4(x[2], y[2], x[3], y[3]);
        dst[2] = make_float4(x[4], y[4], x[5], y[5]);
        dst[3] = make_float4(x[6], y[6], x[7], y[7]);
    }

    u64 key[PER_];
#pragma unroll
    for (int j = 0; j < PER_; j++) {
        unsigned i  = (unsigned)(t * PER_ + j);
        unsigned u  = __float_as_uint(sv[j]);
        unsigned os = u ^ (0x80000000u | (unsigned)(((int)u) >> 31)); // order-preserving
        key[j] = ((u64)os << 32) | (u64)(0xFFFFFFFFu - i);
    }

    // Initial local best (no picks yet -> no validation needed).
    u64 bk = key[0]; float bx = x[0], by = y[0];
#pragma unroll
    for (int j = 1; j < PER_; j++)
        if (key[j] > bk) { bk = key[j]; bx = x[j]; by = y[j]; }

    float px[MODES_], py[MODES_];   // pick history (static-indexed -> registers)
    float gbuf[MODES_];             // gather buffer (gather threads only)
    unsigned wmask = 0;             // bit m set <=> round m had a winner

    const bool is_gather = (t >= TPB_ - 64) && (t - (TPB_ - 64) < 60);
    const int  ge        = t - (TPB_ - 64);   // gather element (valid if is_gather)

    __syncthreads();   // sgoal ready

#pragma unroll
    for (int m = 0; m < MODES_; m++) {
        // --- warp max over the 32 lazy local-bests (5 shfl levels) ---
        u64 best = bk;
#pragma unroll
        for (int o = 16; o > 0; o >>= 1) {
            u64 v = __shfl_xor_sync(0xFFFFFFFFu, best, o);
            best = v > best ? v : best;
        }
        if (lane == 0) red[m & 1][w] = best;
        __syncthreads();   // ONLY barrier this round

        // --- all threads merge the 16 warp partials (8x LDS.128) ---
        const ulonglong2* rp = (const ulonglong2*)red[m & 1];
        u64 win = 0ull;
#pragma unroll
        for (int q = 0; q < NW_ / 2; q++) {
            ulonglong2 p = rp[q];
            u64 hi = p.x > p.y ? p.x : p.y;
            win = hi > win ? hi : win;
        }
        if (t == 0) win_s[m] = win;

        if (win != 0ull) {
            wmask |= 1u << m;
            const int widx = (int)(0xFFFFFFFFu - (unsigned)(win & 0xFFFFFFFFull));
            const float2 g = sgoal[widx];      // broadcast read
            px[m] = g.x; py[m] = g.y;

            // --- gather: ISSUE ONLY (value consumed after the loop) ---
            if (is_gather) gbuf[m] = __ldg(tb + (size_t)ge * N_ + widx);

            // --- lazy update of local best (skipped after the final pick) ---
            if (m < MODES_ - 1) {
                float dx = bx - g.x, dy = by - g.y;
                bool need = (bk == win) | (bk != 0ull && dx * dx + dy * dy < THRESH2_);
                if (need) {
#pragma unroll
                    for (int j = 0; j < PER_; j++) key[j] = (key[j] == bk) ? 0ull : key[j];
                    for (;;) {   // rare path: recompute + validate vs pick history
                        u64 nk = key[0]; float nx = x[0], ny = y[0];
#pragma unroll
                        for (int j = 1; j < PER_; j++)
                            if (key[j] > nk) { nk = key[j]; nx = x[j]; ny = y[j]; }
                        if (nk == 0ull) { bk = 0ull; break; }
                        bool sup = false;
#pragma unroll
                        for (int r = 0; r < MODES_; r++) {
                            if (r <= m) {
                                float ddx = nx - px[r], ddy = ny - py[r];
                                sup |= (ddx * ddx + ddy * ddy < THRESH2_);
                            }
                        }
                        if (sup) {
#pragma unroll
                            for (int j = 0; j < PER_; j++) key[j] = (key[j] == nk) ? 0ull : key[j];
                        } else { bk = nk; bx = nx; by = ny; break; }
                    }
                }
            }
        }
        // no trailing barrier: next round writes the other parity buffer; the
        // round-(m+1) barrier bounds warp skew to one round.
    }

    // --- gather epilogue: 6 STGs per gather thread; fallback modes reuse
    //     round-0's value (round 0 always has a winner: all keys nonzero) ---
    if (is_gather) {
#pragma unroll
        for (int m = 0; m < MODES_; m++) {
            ob[m * 60 + ge] = (wmask & (1u << m)) ? gbuf[m] : gbuf[0];
        }
    }

    __syncthreads();   // win_s[] complete

    // scores (empty slot -> round-0 winner = global top-1)
    if (t < MODES_) {
        u64 wv = win_s[t];
        if (wv == 0ull) wv = win_s[0];
        unsigned os = (unsigned)(wv >> 32);
        out[(size_t)B_ * MODES_ * 60 + (size_t)b * MODES_ + t] =
            __uint_as_float(os ^ (0x80000000u | (unsigned)(((int)~os) >> 31)));
    }
}

extern "C" void kernel_launch(void* const* d_in, const int* in_sizes, int n_in,
                              void* d_out, int out_size)
{
    const float* goals_scores = (const float*)d_in[0];  // [128, 4096]
    const float* traj_preds   = (const float*)d_in[1];  // [128, 60, 4096]
    const float* pred_goals   = (const float*)d_in[2];  // [128, 2, 4096]
    float* out = (float*)d_out;

    densetnt_nms_kernel<<<B_, TPB_>>>(goals_scores, traj_preds, pred_goals, out);
}